// round 17
// baseline (speedup 1.0000x reference)
#include <cuda_runtime.h>
#include <math.h>
#include <stdint.h>

#define NUM_B   4
#define SEQ_T   4096
#define NTOK    (NUM_B*SEQ_T)      // 16384
#define MODEL   2048
#define RANK    16
#define DD      1024               // NUM_HEADS * PE_DIM
#define QK_ELEMS 33554432          // NTOK*16*128

typedef unsigned long long ull;

// scratch (allocation-free rule: __device__ globals)
__device__ float g_u[NTOK*RANK];   // x_norm @ W1
__device__ float g_U[NTOK*RANK];   // cumsum over t of g_u

// ---- packed f32x2 helpers (sm_103a FFMA2 path, PTX-only) --------------------
__device__ __forceinline__ ull pk2(float a, float b) {
    ull r;
    asm("mov.b64 %0, {%1, %2};" : "=l"(r) : "f"(a), "f"(b));
    return r;
}
__device__ __forceinline__ void fma2(ull& d, ull a, ull b) {
    asm("fma.rn.f32x2 %0, %1, %2, %0;" : "+l"(d) : "l"(a), "l"(b));
}
__device__ __forceinline__ ull add2(ull a, ull b) {
    ull r;
    asm("add.rn.f32x2 %0, %1, %2;" : "=l"(r) : "l"(a), "l"(b));
    return r;
}
__device__ __forceinline__ void upk2(ull v, float& a, float& b) {
    asm("mov.b64 {%0, %1}, %2;" : "=f"(a), "=f"(b) : "l"(v));
}
__device__ __forceinline__ float fcomp(float4 v, int i) {
    switch (i) { case 0: return v.x; case 1: return v.y; case 2: return v.z; default: return v.w; }
}
// streaming (evict-first) loads/stores
__device__ __forceinline__ float4 ldcs4(const float* p) {
    float4 v;
    asm volatile("ld.global.cs.v4.f32 {%0,%1,%2,%3}, [%4];"
                 : "=f"(v.x), "=f"(v.y), "=f"(v.z), "=f"(v.w) : "l"(p));
    return v;
}
__device__ __forceinline__ float2 ldcs2(const float* p) {
    float2 v;
    asm volatile("ld.global.cs.v2.f32 {%0,%1}, [%2];"
                 : "=f"(v.x), "=f"(v.y) : "l"(p));
    return v;
}
__device__ __forceinline__ void stcs2(float* p, float2 v) {
    asm volatile("st.global.cs.v2.f32 [%0], {%1,%2};"
                 :: "l"(p), "f"(v.x), "f"(v.y) : "memory");
}

// ---- kA inner body (one 4-token task; W1 plane resident in smem) -----------
__device__ __forceinline__ void kA_task(const float* __restrict__ hid,
                                        const ull* __restrict__ Wsu,
                                        int tok, int lane)
{
    const float* xg = hid + (size_t)tok*MODEL + lane*4;

    float4 xq[2][4];
    #pragma unroll
    for (int pf = 0; pf < 2; ++pf)
        #pragma unroll
        for (int t = 0; t < 4; ++t)
            xq[pf][t] = ldcs4(xg + (size_t)t*MODEL + pf*128);

    ull acc[4][8];
    #pragma unroll
    for (int t = 0; t < 4; ++t)
        #pragma unroll
        for (int r = 0; r < 8; ++r) acc[t][r] = 0ull;

    #pragma unroll
    for (int c = 0; c < 16; ++c) {
        const int buf = c & 1;

        float ss[4];
        #pragma unroll
        for (int t = 0; t < 4; ++t) {
            float4 v = xq[buf][t];
            ss[t] = v.x*v.x + v.y*v.y + v.z*v.z + v.w*v.w;
        }
        #pragma unroll
        for (int o = 16; o > 0; o >>= 1) {
            #pragma unroll
            for (int t = 0; t < 4; ++t)
                ss[t] += __shfl_xor_sync(0xffffffffu, ss[t], o);
        }
        float inv[4];
        #pragma unroll
        for (int t = 0; t < 4; ++t) inv[t] = rsqrtf(ss[t] + 1e-6f);

        const ull* wc = Wsu + c*1024 + lane;
        #pragma unroll
        for (int dd = 0; dd < 4; ++dd) {
            ull xpt[4];
            #pragma unroll
            for (int t = 0; t < 4; ++t) {
                const float xs = fcomp(xq[buf][t], dd) * inv[t];
                xpt[t] = pk2(xs, xs);
            }
            const ull* wp = wc + dd*256;
            #pragma unroll
            for (int rp = 0; rp < 8; ++rp) {
                const ull w = wp[rp*32];
                #pragma unroll
                for (int t = 0; t < 4; ++t)
                    fma2(acc[t][rp], xpt[t], w);
            }
        }

        if (c < 14) {
            #pragma unroll
            for (int t = 0; t < 4; ++t)
                xq[buf][t] = ldcs4(xg + (size_t)t*MODEL + (c+2)*128);
        }
    }

    ull v[32];
    #pragma unroll
    for (int t = 0; t < 4; ++t)
        #pragma unroll
        for (int rp = 0; rp < 8; ++rp)
            v[t*8 + rp] = acc[t][rp];

    #pragma unroll
    for (int o = 16; o >= 1; o >>= 1) {
        const bool up = (lane & o) != 0;
        #pragma unroll
        for (int j = 0; j < o; ++j) {
            ull send = up ? v[j] : v[j + o];
            ull keep = up ? v[j + o] : v[j];
            v[j] = add2(keep, __shfl_xor_sync(0xffffffffu, send, o));
        }
    }
    *(ull*)(g_u + (tok + (lane >> 3))*RANK + (lane & 7)*2) = v[0];
}

__device__ __forceinline__ void stage_W1(float* Wsm, const float* __restrict__ W1,
                                         int tid)
{
    // plane layout: word addr = ((c*4+dd)*8 + rp)*64 + l*2 + hi
    for (int idx = tid; idx < MODEL*RANK; idx += 512) {
        const int d = idx >> 4, r = idx & 15;
        const int c = d >> 7, l = (d >> 2) & 31, dd = d & 3;
        Wsm[((((c << 2) + dd) << 3) + (r >> 1))*64 + l*2 + (r & 1)] = W1[idx];
    }
}

// ---------------------------------------------------------------------------
// kA1: standalone kA for ONE batch, spread over 128 blocks (8 active warps/SM)
// ---------------------------------------------------------------------------
__global__ __launch_bounds__(512) void kA1(const float* __restrict__ hid,
                                           const float* __restrict__ W1,
                                           int b)
{
    extern __shared__ float Wsm[];
    const int tid  = threadIdx.x;
    const int lane = tid & 31;
    const int wid  = tid >> 5;

    stage_W1(Wsm, W1, tid);
    __syncthreads();

    const int gw = blockIdx.x*16 + wid;       // 0..2047
    if (gw & 1) return;                       // half-density: 8 warps/SM active
    const int task = gw >> 1;                 // 0..1023
    kA_task(hid, (const ull*)Wsm, b*SEQ_T + task*4, lane);
}

// ---------------------------------------------------------------------------
// kB(b): inclusive cumsum over t for batch b. grid 16 (r), 1024 threads.
// ---------------------------------------------------------------------------
__global__ __launch_bounds__(1024) void kB(int b)
{
    __shared__ float wsum[32];
    const int r = blockIdx.x;
    const int tid = threadIdx.x, lane = tid & 31, wid = tid >> 5;
    const float* up = g_u + ((size_t)b*SEQ_T)*RANK + r;
    const int t = tid*4;
    float u0 = up[(t+0)*RANK];
    float u1 = up[(t+1)*RANK];
    float u2 = up[(t+2)*RANK];
    float u3 = up[(t+3)*RANK];
    float v0 = u0, v1 = v0+u1, v2 = v1+u2, v3 = v2+u3;
    float s = v3;
    #pragma unroll
    for (int o = 1; o < 32; o <<= 1) { float n = __shfl_up_sync(0xffffffffu, s, o); if (lane >= o) s += n; }
    if (lane == 31) wsum[wid] = s;
    __syncthreads();
    if (wid == 0) {
        float ws = wsum[lane];
        #pragma unroll
        for (int o = 1; o < 32; o <<= 1) { float n = __shfl_up_sync(0xffffffffu, ws, o); if (lane >= o) ws += n; }
        wsum[lane] = ws;
    }
    __syncthreads();
    const float base = (wid > 0) ? wsum[wid-1] : 0.f;
    const float excl = base + s - v3;
    float* Up = g_U + ((size_t)b*SEQ_T)*RANK + r;
    Up[(t+0)*RANK] = excl + v0;
    Up[(t+1)*RANK] = excl + v1;
    Up[(t+2)*RANK] = excl + v2;
    Up[(t+3)*RANK] = excl + v3;
}

// ---------------------------------------------------------------------------
// kF: fused spatial-partition kernel. 192 blocks x 512 thr, smem 131 KB.
//   bid%3==2 (64 blocks) -> kA role for batch bA (16 warps x 1 task).
//   else     (128 blocks) -> kC role for batch bC (32 tokens, 2 d/thread).
//   bA<0 / bC<0 disables the respective role (early whole-block exit).
// ---------------------------------------------------------------------------
__global__ __launch_bounds__(512) void kF(const float* __restrict__ q,
                                          const float* __restrict__ k,
                                          const float* __restrict__ hid,
                                          const float* __restrict__ W1,
                                          const float* __restrict__ W2,
                                          const float* __restrict__ cw,
                                          float* __restrict__ out,
                                          int bC, int bA)
{
    extern __shared__ float sm[];
    const int bid = blockIdx.x;
    const int tid = threadIdx.x;

    if ((bid % 3) == 2) {
        // ---------------- kA role ----------------
        if (bA < 0) return;
        const int lane = tid & 31;
        const int wid  = tid >> 5;
        stage_W1(sm, W1, tid);
        __syncthreads();
        const int task = (bid/3)*16 + wid;        // 0..1023
        kA_task(hid, (const ull*)sm, bA*SEQ_T + task*4, lane);
        return;
    }

    // ---------------- kC role ----------------
    if (bC < 0) return;
    float* PDs = sm;                 // [11][1024]
    float* Us  = sm + 11*1024;       // [35][16]
    const int cIdx = (bid/3)*2 + (bid%3);         // 0..127
    const int t0   = cIdx * 32;                   // within batch
    const int tok0 = bC*SEQ_T + t0;

    for (int i = tid; i < 35*RANK; i += 512) {
        const int row = t0 - 3 + (i >> 4);
        Us[i] = (row < 0) ? 0.f : g_U[(((size_t)bC << 12) + row)*RANK + (i & 15)];
    }

    const int d0 = tid << 1;                      // 2 d per thread (even)
    const int hh = d0 >> 6;
    const size_t qoff0 = (size_t)(hh << 6) + d0;  // h*128 + j0
    const int j0 = d0 & 63;
    const float LNT = 0.20503692775998528f;       // ln(500000)/64
    const float tv0 = expf(-LNT*(float)j0);
    const float tv1 = expf(-LNT*(float)(j0+1));

    ull w2a[16];
    #pragma unroll
    for (int r = 0; r < 16; ++r) {
        float2 w = *(const float2*)(W2 + r*DD + d0);
        w2a[r] = pk2(w.x, w.y);
    }
    ull cva[4];
    #pragma unroll
    for (int w = 0; w < 4; ++w) {
        float2 c = *(const float2*)(cw + w*DD + d0);
        cva[w] = pk2(c.x*tv0, c.y*tv1);
    }
    __syncthreads();

    for (int g = 0; g < 4; ++g) {
        // phase P (packed FFMA2): PD rows for tokens [g*8-3 .. g*8+7]
        #pragma unroll
        for (int row = 0; row < 11; ++row) {
            const float* Ur = Us + (g*8 + row)*RANK;
            ull a01 = 0ull;
            #pragma unroll
            for (int r = 0; r < 16; ++r) {
                const float u = Ur[r];
                fma2(a01, pk2(u, u), w2a[r]);
            }
            *(ull*)(PDs + row*DD + d0) = a01;
        }
        __syncthreads();

        // phase R: 8 tokens, packed conv -> angle -> sincos -> rotate
        for (int i = 0; i < 8; ++i) {
            const int tok = tok0 + g*8 + i;
            ull aA = 0ull;
            fma2(aA, cva[0], *(const ull*)(PDs + (i    )*DD + d0));
            fma2(aA, cva[1], *(const ull*)(PDs + (i + 1)*DD + d0));
            fma2(aA, cva[2], *(const ull*)(PDs + (i + 2)*DD + d0));
            fma2(aA, cva[3], *(const ull*)(PDs + (i + 3)*DD + d0));

            float ax, ay;
            upk2(aA, ax, ay);
            float s0, c0, s1, c1;
            __sincosf(ax, &s0, &c0);
            __sincosf(ay, &s1, &c1);

            const size_t base = (size_t)tok*2048 + qoff0;
            float2 q0 = ldcs2(q + base);
            float2 q1 = ldcs2(q + base + 64);
            float2 k0 = ldcs2(k + base);
            float2 k1 = ldcs2(k + base + 64);

            float2 o0, o1;
            o0.x = q0.x*c0 - q1.x*s0;  o1.x = q0.x*s0 + q1.x*c0;
            o0.y = q0.y*c1 - q1.y*s1;  o1.y = q0.y*s1 + q1.y*c1;
            stcs2(out + base,      o0);
            stcs2(out + base + 64, o1);

            o0.x = k0.x*c0 - k1.x*s0;  o1.x = k0.x*s0 + k1.x*c0;
            o0.y = k0.y*c1 - k1.y*s1;  o1.y = k0.y*s1 + k1.y*c1;
            stcs2(out + QK_ELEMS + base,      o0);
            stcs2(out + QK_ELEMS + base + 64, o1);
        }
        __syncthreads();
    }
}

// ---------------------------------------------------------------------------
// Launch: software-pipelined over batches in ONE stream:
//   kA1(0); kB(0); kF(C0,A1); kB(1); kF(C1,A2); kB(2); kF(C2,A3); kB(3); kF(C3,-)
// ---------------------------------------------------------------------------
extern "C" void kernel_launch(void* const* d_in, const int* in_sizes, int n_in,
                              void* d_out, int out_size)
{
    const float* q   = (const float*)d_in[0];
    const float* k   = (const float*)d_in[1];
    const float* hid = (const float*)d_in[2];
    const float* W1  = (const float*)d_in[3];
    const float* W2  = (const float*)d_in[4];
    const float* cw  = (const float*)d_in[5];
    float* out = (float*)d_out;

    const int SMEM_F = MODEL*RANK*4;                 // 131072 B
    cudaFuncSetAttribute(kA1, cudaFuncAttributeMaxDynamicSharedMemorySize, SMEM_F);
    cudaFuncSetAttribute(kF,  cudaFuncAttributeMaxDynamicSharedMemorySize, SMEM_F);

    kA1<<<128, 512, SMEM_F>>>(hid, W1, 0);
    kB<<<RANK, 1024>>>(0);
    kF<<<192, 512, SMEM_F>>>(q, k, hid, W1, W2, cw, out, 0, 1);
    kB<<<RANK, 1024>>>(1);
    kF<<<192, 512, SMEM_F>>>(q, k, hid, W1, W2, cw, out, 1, 2);
    kB<<<RANK, 1024>>>(2);
    kF<<<192, 512, SMEM_F>>>(q, k, hid, W1, W2, cw, out, 2, 3);
    kB<<<RANK, 1024>>>(3);
    kF<<<192, 512, SMEM_F>>>(q, k, hid, W1, W2, cw, out, 3, -1);
}